// round 6
// baseline (speedup 1.0000x reference)
#include <cuda_runtime.h>
#include <cstdint>

typedef unsigned long long ull;

// Problem: x (8,256,128,128) f32 -> out (8,256,64,64) f32
// CARAFE downsample: 1x1 conv(256->64) . 3x3 s2 conv(64->25) . softmax . 5x5 s2 gather
// Fully fused: one kernel streams x twice per tile (pass2 descending, L2/smem reuse).

#define RFLT   40            // padded floats per staged row (10 quads)
#define RQ     10            // float4 chunks per row
#define RROWS  19            // staged rows per channel
#define CHF    760           // floats per channel plane (19*40)
#define STGF   1520          // floats per stage (2 channels)
#define NCHUNK 380           // 16B chunks per stage
#define NCACHE 16            // cached channel-pairs (cps 112..127)

// dynamic smem float offsets
#define OFF_XS    0
#define OFF_CACHE 4560        // 3*1520
#define OFF_WS    28880       // +16*1520
#define OFF_BT    30284       // +1404
#define OFF_BK    30572
#define SMEM_BYTES (30604 * 4)

// ---- persistent device scratch ----
__device__ float4 g_W2[128 * 9 * 13];   // [cp][tap][kk]{w2k_c0,w2k_c1,w2k1_c0,w2k1_c1}
__device__ float  g_btap[9 * 32];       // per-tap bias (b_comp through encoder)
__device__ float  g_bk[32];             // b_enc * exp(p)

__device__ __forceinline__ ull pack2(float a, float b) {
    ull r; asm("mov.b64 %0, {%1, %2};" : "=l"(r) : "f"(a), "f"(b)); return r;
}
__device__ __forceinline__ void unpack2(ull v, float& a, float& b) {
    asm("mov.b64 {%0, %1}, %2;" : "=f"(a), "=f"(b) : "l"(v));
}
#define FMA2(d, a, b) asm("fma.rn.f32x2 %0, %1, %2, %0;" : "+l"(d) : "l"(a), "l"(b))

__device__ __forceinline__ uint32_t smem_u32(const void* p) {
    return (uint32_t)__cvta_generic_to_shared(p);
}
__device__ __forceinline__ void cpa16(uint32_t dst, const void* src) {
    asm volatile("cp.async.ca.shared.global [%0], [%1], 16;" :: "r"(dst), "l"(src));
}
#define CP_COMMIT() asm volatile("cp.async.commit_group;")
template<int N> __device__ __forceinline__ void cp_wait() {
    asm volatile("cp.async.wait_group %0;" :: "n"(N));
}

// ============================================================================
// Kernel 1: fuse compressor+encoder weights. 225 blocks (k,tap) x 256 threads.
// ============================================================================
__global__ void prep_kernel(const float* __restrict__ w_comp, const float* __restrict__ b_comp,
                            const float* __restrict__ w_enc, const float* __restrict__ b_enc,
                            const float* __restrict__ power_p) {
    int k = blockIdx.x / 9, tap = blockIdx.x % 9;
    int c = threadIdx.x;
    __shared__ float we[64];
    float expP = __expf(power_p[0]);
    if (c < 64) we[c] = w_enc[(k * 64 + c) * 9 + tap];
    __syncthreads();
    float s = 0.f;
#pragma unroll 8
    for (int cc = 0; cc < 64; cc++) s += we[cc] * w_comp[cc * 256 + c];
    s *= expP;
    float* W2f = (float*)g_W2;
    int cp = c >> 1, kk = k >> 1;
    W2f[((cp * 9 + tap) * 13 + kk) * 4 + (k & 1) * 2 + (c & 1)] = s;
    if (k == 0 && c < 128) {  // zero k=25 pad lanes
        W2f[((c * 9 + tap) * 13 + 12) * 4 + 2] = 0.f;
        W2f[((c * 9 + tap) * 13 + 12) * 4 + 3] = 0.f;
    }
    if (c == 0) {
        float bs = 0.f;
        for (int cc = 0; cc < 64; cc++) bs += we[cc] * b_comp[cc];
        g_btap[tap * 32 + k] = bs * expP;
        if (tap == 0) g_bk[k] = b_enc[k] * expP;
    }
}

// ============================================================================
// Kernel 2: FUSED logits + softmax + aggregate.
// 256 blocks: [b(8)][tile(32): 4x(16w) x 8x(8h)], 128 threads, 1 px/thread.
// Pass 1: stream cps 0..127 ascending (last 16 land in smem cache), logit conv.
// Softmax locally. Pass 2: stream cps 127..0 descending (cache + L2 reuse),
// 25-tap gather, write out.
// ============================================================================
__global__ __launch_bounds__(128) void fused_kernel(const float* __restrict__ x,
                                                    float* __restrict__ out) {
    extern __shared__ __align__(16) float sm[];
    int bid  = blockIdx.x;
    int b    = bid >> 5;
    int t    = bid & 31;
    int w0 = (t & 3) * 16;
    int h0 = (t >> 2) * 8;
    int tid = threadIdx.x;
    int px = tid & 15;
    int py = tid >> 4;
    int h = h0 + py, w = w0 + px;

    float* XS = sm + OFF_XS;
    float* CA = sm + OFF_CACHE;
    float* WS = sm + OFF_WS;
    float* BT = sm + OFF_BT;
    float* BK = sm + OFF_BK;

    for (int i = tid; i < 288; i += 128) BT[i] = g_btap[i];
    if (tid < 32) BK[tid] = g_bk[tid];
    // pre-zero stages + cache: OOB chunks stay zero forever
    for (int i = tid; i < OFF_WS; i += 128) sm[i] = 0.f;

    // ---- one-time chunk addressing (3 chunk-slots per thread) ----
    int goff[3];
    unsigned vmask = 0;
#pragma unroll
    for (int j = 0; j < 3; j++) {
        int idx = tid + j * 128;
        int ch = 0, row = 0, col = 0;
        bool ok = idx < NCHUNK;
        if (ok) {
            ch = idx / 190; int rem = idx - ch * 190;
            int r = rem / RQ, q = rem - r * RQ;
            row = 2 * h0 - 2 + r;
            col = 2 * w0 - 4 + 4 * q;
            ok = (row >= 0) && (row < 128) && (col >= 0) && (col <= 124);
        }
        if (ok) vmask |= 1u << j;
        goff[j] = ch * 16384 + row * 128 + col;
    }
    // per-slot smem byte offsets within a stage
    uint32_t soff[3];
#pragma unroll
    for (int j = 0; j < 3; j++) {
        int idx = tid + j * 128;
        if (idx >= NCHUNK) idx = 0;        // masked-off anyway
        int ch = idx / 190; int rem = idx - ch * 190;
        int r = rem / RQ, q = rem - r * RQ;
        soff[j] = (uint32_t)((ch * CHF + r * RFLT + 4 * q) * 4);
    }
    uint32_t xs_addr = smem_u32(XS);
    uint32_t ca_addr = smem_u32(CA);
    uint32_t ws_addr = smem_u32(WS);
    const float* xb = x + (size_t)b * 256 * 16384;

    auto xfill = [&](int cp) {     // x chunks -> stage (cp%3) or cache (cp>=112)
        uint32_t base = (cp >= 112) ? (ca_addr + (uint32_t)(cp - 112) * (STGF * 4))
                                    : (xs_addr + (uint32_t)(cp % 3) * (STGF * 4));
        const float* xc = xb + (size_t)(2 * cp) * 16384;
#pragma unroll
        for (int j = 0; j < 3; j++)
            if (vmask & (1u << j)) cpa16(base + soff[j], xc + goff[j]);
    };
    auto wfill = [&](int cp) {
        if (tid < 117) cpa16(ws_addr + (uint32_t)(cp % 3) * 1872 + (uint32_t)tid * 16,
                             &g_W2[cp * 117 + tid]);
    };
    auto stage_ptr = [&](int cp) -> const float* {
        return (cp >= 112) ? (CA + (cp - 112) * STGF) : (XS + (cp % 3) * STGF);
    };

    // ================= PASS 1: logits =================
    ull acc[26];
#pragma unroll
    for (int i = 0; i < 26; i++) acc[i] = 0ull;

    __syncthreads();
    xfill(0); wfill(0); CP_COMMIT();
    xfill(1); wfill(1); CP_COMMIT();
#pragma unroll 1
    for (int i = 0; i < 128; i++) {
        __syncthreads();
        if (i + 2 < 128) { xfill(i + 2); wfill(i + 2); }
        CP_COMMIT();
        cp_wait<2>();
        __syncthreads();

        const float* rp = stage_ptr(i);
        const ulonglong2* wsb = (const ulonglong2*)(WS + (i % 3) * 468);
#pragma unroll
        for (int dy = 0; dy < 3; dy++) {
#pragma unroll
            for (int dx = 0; dx < 3; dx++) {
                const float* p = rp + (2 * py + 1 + dy) * RFLT + (2 * px + 3 + dx);
                ull xv = pack2(p[0], p[CHF]);
                const ulonglong2* wp = wsb + (dy * 3 + dx) * 13;
#pragma unroll
                for (int kk = 0; kk < 13; kk++) {
                    ulonglong2 wv = wp[kk];
                    FMA2(acc[2 * kk],     wv.x, xv);
                    FMA2(acc[2 * kk + 1], wv.y, xv);
                }
            }
        }
    }

    // ================= softmax (local, per-thread px) =================
    ull mp[5][3];
    {
        float logit[25];
#pragma unroll
        for (int k = 0; k < 25; k++) {
            float a, c2;
            unpack2(acc[k], a, c2);
            logit[k] = a + c2 + BK[k];
        }
#pragma unroll
        for (int tap = 0; tap < 9; tap++) {
            int dy = tap / 3, dx = tap % 3;
            bool inb = (2 * h - 1 + dy >= 0) && (2 * w - 1 + dx >= 0) && (2 * w - 1 + dx < 128);
            if (inb) {
#pragma unroll
                for (int k = 0; k < 25; k++) logit[k] += BT[tap * 32 + k];
            }
        }
        float mx = logit[0];
#pragma unroll
        for (int k = 1; k < 25; k++) mx = fmaxf(mx, logit[k]);
        float sum = 0.f;
#pragma unroll
        for (int k = 0; k < 25; k++) { logit[k] = __expf(logit[k] - mx); sum += logit[k]; }
        float inv = 1.f / sum;
#pragma unroll
        for (int k = 0; k < 25; k++) logit[k] *= inv;
#pragma unroll
        for (int di = 0; di < 5; di++) {
            mp[di][0] = pack2(logit[5 * di],     logit[5 * di + 1]);
            mp[di][1] = pack2(logit[5 * di + 2], logit[5 * di + 3]);
            mp[di][2] = pack2(logit[5 * di + 4], 0.f);
        }
    }

    // ================= PASS 2: aggregate, descending =================
    float* ob = out + (((size_t)b * 256) << 12) + (h << 6) + w;
    __syncthreads();
    xfill(111); CP_COMMIT();
    xfill(110); CP_COMMIT();

#pragma unroll 1
    for (int j = 0; j < 128; j++) {
        int cp = 127 - j;
        __syncthreads();
        int cpf = cp - 2;
        if (cpf >= 0 && cpf <= 109) xfill(cpf);
        CP_COMMIT();
        cp_wait<2>();
        __syncthreads();

        const float* rp = stage_ptr(cp);
        ull accA = 0ull, accB = 0ull;
#pragma unroll
        for (int di = 0; di < 5; di++) {
            const float* rowp = rp + (2 * py + di) * RFLT + (2 * px + 2);
            ull x0 = *(const ull*)(rowp);
            ull x1 = *(const ull*)(rowp + 2);
            ull x2 = *(const ull*)(rowp + 4);
            FMA2(accA, mp[di][0], x0);
            FMA2(accA, mp[di][1], x1);
            FMA2(accA, mp[di][2], x2);
            ull y0 = *(const ull*)(rowp + CHF);
            ull y1 = *(const ull*)(rowp + CHF + 2);
            ull y2 = *(const ull*)(rowp + CHF + 4);
            FMA2(accB, mp[di][0], y0);
            FMA2(accB, mp[di][1], y1);
            FMA2(accB, mp[di][2], y2);
        }
        float a0, a1, b0, b1;
        unpack2(accA, a0, a1);
        unpack2(accB, b0, b1);
        ob[((size_t)(2 * cp)) << 12]       = a0 + a1;
        ob[((size_t)(2 * cp + 1)) << 12]   = b0 + b1;
    }
}

// ============================================================================
extern "C" void kernel_launch(void* const* d_in, const int* in_sizes, int n_in,
                              void* d_out, int out_size) {
    const float* x       = (const float*)d_in[0];
    const float* w_comp  = (const float*)d_in[1];
    const float* b_comp  = (const float*)d_in[2];
    const float* w_enc   = (const float*)d_in[3];
    const float* b_enc   = (const float*)d_in[4];
    const float* power_p = (const float*)d_in[5];
    float* out = (float*)d_out;

    cudaFuncSetAttribute(fused_kernel, cudaFuncAttributeMaxDynamicSharedMemorySize, SMEM_BYTES);
    prep_kernel<<<225, 256>>>(w_comp, b_comp, w_enc, b_enc, power_p);
    fused_kernel<<<256, 128, SMEM_BYTES>>>(x, out);
}

// round 7
// speedup vs baseline: 1.3029x; 1.3029x over previous
#include <cuda_runtime.h>
#include <cstdint>

typedef unsigned long long ull;

// Problem: x (8,256,128,128) f32 -> out (8,256,64,64) f32
// CARAFE downsample: 1x1 conv(256->64) . 3x3 s2 conv(64->25) . softmax . 5x5 s2 gather

// logits staging: tile 16w x 8h px -> region 17 rows x 36 cols, 2 ch planes
#define L_RFLT  36
#define L_CHF   612       // 17*36
#define L_STGF  1224
#define L_CHUNK 306       // 16B chunks per stage
// aggregate staging: tile 16w x 8h px -> region 19 rows x 40 cols, 2 ch planes
#define A_RFLT  40
#define A_CHF   760       // 19*40
#define A_STGF  1520
#define A_CHUNK 380

// ---- persistent device scratch ----
// fused weights: [cp](9 taps x 14 kk) float4 {w[2kk][c0],w[2kk][c1],w[2kk+1][c0],w[2kk+1][c1]}
__device__ float4 g_W2[128 * 126];
__device__ float  g_btap[9 * 32];          // per-tap border bias (b_comp via encoder)
__device__ float  g_bk[32];                // b_enc * exp(p)
__device__ float  g_mask[8 * 25 * 4096];   // softmaxed masks [b][k][h][w]

__device__ __forceinline__ ull pack2(float a, float b) {
    ull r; asm("mov.b64 %0, {%1, %2};" : "=l"(r) : "f"(a), "f"(b)); return r;
}
__device__ __forceinline__ void unpack2(ull v, float& a, float& b) {
    asm("mov.b64 {%0, %1}, %2;" : "=f"(a), "=f"(b) : "l"(v));
}
#define FMA2(d, a, b) asm("fma.rn.f32x2 %0, %1, %2, %0;" : "+l"(d) : "l"(a), "l"(b))

__device__ __forceinline__ uint32_t smem_u32(const void* p) {
    return (uint32_t)__cvta_generic_to_shared(p);
}
__device__ __forceinline__ void cpa16(uint32_t dst, const void* src) {
    asm volatile("cp.async.ca.shared.global [%0], [%1], 16;" :: "r"(dst), "l"(src));
}
#define CP_COMMIT() asm volatile("cp.async.commit_group;")
template<int N> __device__ __forceinline__ void cp_wait() {
    asm volatile("cp.async.wait_group %0;" :: "n"(N));
}

// ============================================================================
// Kernel 1: fuse compressor+encoder weights. 25 blocks (k) x 256 threads (c).
// ============================================================================
__global__ void prep_kernel(const float* __restrict__ w_comp, const float* __restrict__ b_comp,
                            const float* __restrict__ w_enc, const float* __restrict__ b_enc,
                            const float* __restrict__ power_p) {
    int k = blockIdx.x;
    int c = threadIdx.x;
    __shared__ float we[576];   // [tap*64+cc]
    __shared__ float bc[64];
    float expP = __expf(power_p[0]);
    for (int i = c; i < 576; i += 256) {
        int cc = i / 9, tap = i % 9;
        we[tap * 64 + cc] = w_enc[k * 576 + i];
    }
    if (c < 64) bc[c] = b_comp[c];
    __syncthreads();

    float wc[64];
#pragma unroll
    for (int cc = 0; cc < 64; cc++) wc[cc] = w_comp[cc * 256 + c];   // coalesced

    float* W2f = (float*)g_W2;
    int cp = c >> 1, kk = k >> 1, slot = (k & 1) * 2 + (c & 1);
#pragma unroll 1
    for (int tap = 0; tap < 9; tap++) {
        float s = 0.f;
#pragma unroll
        for (int cc = 0; cc < 64; cc++) s += we[tap * 64 + cc] * wc[cc];
        W2f[((cp * 9 + tap) * 14 + kk) * 4 + slot] = s * expP;
    }
    if (c < 9) {
        float bs = 0.f;
        for (int cc = 0; cc < 64; cc++) bs += we[c * 64 + cc] * bc[cc];
        g_btap[c * 32 + k] = bs * expP;
    }
    if (c == 9) g_bk[k] = b_enc[k] * expP;
    if (k == 0) {   // zero pad lanes: kk=13 (all), kk=12 slots 2,3; bias pads k=25..31
        for (int i = c; i < 1152; i += 256) {   // i = cp*9+tap
            float4 z = make_float4(0.f, 0.f, 0.f, 0.f);
            g_W2[i * 14 + 13] = z;
            W2f[(i * 14 + 12) * 4 + 2] = 0.f;
            W2f[(i * 14 + 12) * 4 + 3] = 0.f;
        }
        if (c < 7) {
            g_bk[25 + c] = 0.f;
            for (int tap = 0; tap < 9; tap++) g_btap[tap * 32 + 25 + c] = 0.f;
        }
    }
}

// ============================================================================
// Kernel 2: fused 3x3-s2 logit conv + softmax -> g_mask.
// 256 blocks: [b(8)][tile(32): 4x(16w) x 8x(8h)], 128 threads.
// thread = px(16) x ksub(2) x py(4); 2 rows per thread (py, py+4);
// ksub halves split the 25 k-outputs (7 kpairs each, pad to 28).
// 4-stage cp.async pipeline, ONE barrier per channel-pair iteration.
// ============================================================================
__global__ __launch_bounds__(128) void logits_kernel(const float* __restrict__ x) {
    int bid = blockIdx.x;
    int b   = bid >> 5;
    int t   = bid & 31;
    int w0 = (t & 3) * 16;
    int h0 = (t >> 2) * 8;
    int tid  = threadIdx.x;
    int px   = tid & 15;
    int ksub = (tid >> 4) & 1;
    int py   = tid >> 5;          // 0..3

    __shared__ __align__(16) float  XS[4 * L_STGF];
    __shared__ __align__(16) float4 WS4[4 * 126];
    __shared__ float BT[288];
    __shared__ float BK[32];

    for (int i = tid; i < 4 * L_STGF; i += 128) XS[i] = 0.f;
    for (int i = tid; i < 288; i += 128) BT[i] = g_btap[i];
    if (tid < 32) BK[tid] = g_bk[tid];

    // one-time chunk addressing: 3 slots/thread over 306 chunks
    int goff[3]; bool vld[3]; uint32_t soff[3];
#pragma unroll
    for (int j = 0; j < 3; j++) {
        int idx = tid + j * 128;
        bool ok = idx < L_CHUNK;
        int ch = 0, r = 0, q = 0, row = 0, col = 0;
        if (ok) {
            ch = idx / 153; int rem = idx - ch * 153;
            r = rem / 9; q = rem - r * 9;
            row = 2 * h0 - 1 + r;
            col = 2 * w0 - 4 + 4 * q;
            ok = (row >= 0) && (col >= 0) && (col <= 124);
        }
        vld[j]  = ok;
        goff[j] = ok ? (ch * 16384 + (row << 7) + col) : 0;
        soff[j] = ok ? (uint32_t)((ch * L_CHF + r * L_RFLT + 4 * q) * 4) : 0u;
    }
    uint32_t xsa = smem_u32(XS), wsa = smem_u32(WS4);
    const float* xb = x + (size_t)b * 256 * 16384;

    auto fill = [&](int s, int cp) {
        const float* xc = xb + (size_t)(2 * cp) * 16384;
        uint32_t base = xsa + (uint32_t)s * (L_STGF * 4);
#pragma unroll
        for (int j = 0; j < 3; j++)
            if (vld[j]) cpa16(base + soff[j], xc + goff[j]);
        if (tid < 126) cpa16(wsa + (uint32_t)s * 2016 + (uint32_t)tid * 16, &g_W2[cp * 126 + tid]);
    };

    ull acc[2][14];
#pragma unroll
    for (int p = 0; p < 2; p++)
#pragma unroll
        for (int j = 0; j < 14; j++) acc[p][j] = 0ull;

    int kk0 = ksub * 7;
    __syncthreads();                 // zeros visible before fills
    fill(0, 0); CP_COMMIT();
    fill(1, 1); CP_COMMIT();

#pragma unroll 1
    for (int i = 0; i < 128; i++) {
        if (i + 2 < 128) fill((i + 2) & 3, i + 2);
        CP_COMMIT();
        cp_wait<2>();
        __syncthreads();

        const float* rp = XS + (i & 3) * L_STGF;
        const ulonglong2* wp = (const ulonglong2*)(WS4 + (i & 3) * 126);
#pragma unroll
        for (int dy = 0; dy < 3; dy++) {
#pragma unroll
            for (int dx = 0; dx < 3; dx++) {
                const float* pA = rp + (2 * py + dy) * L_RFLT + 2 * px + 3 + dx;
                const float* pB = pA + 8 * L_RFLT;
                ull xa = pack2(pA[0], pA[L_CHF]);
                ull xc2 = pack2(pB[0], pB[L_CHF]);
                const ulonglong2* wt = wp + (dy * 3 + dx) * 14 + kk0;
#pragma unroll
                for (int j = 0; j < 7; j++) {
                    ulonglong2 wv = wt[j];
                    FMA2(acc[0][2 * j],     wv.x, xa);
                    FMA2(acc[0][2 * j + 1], wv.y, xa);
                    FMA2(acc[1][2 * j],     wv.x, xc2);
                    FMA2(acc[1][2 * j + 1], wv.y, xc2);
                }
            }
        }
    }

    // epilogue: bias + border + softmax (k halves combined via shfl_xor 16)
    int w = w0 + px;
#pragma unroll
    for (int p = 0; p < 2; p++) {
        int h = h0 + py + 4 * p;
        float lg[14];
#pragma unroll
        for (int tt = 0; tt < 14; tt++) {
            float lo, hi;
            unpack2(acc[p][tt], lo, hi);
            lg[tt] = lo + hi + BK[14 * ksub + tt];
        }
#pragma unroll
        for (int tap = 0; tap < 9; tap++) {
            int dy = tap / 3, dx = tap % 3;
            bool inb = (2 * h - 1 + dy >= 0) && (2 * w - 1 + dx >= 0) && (2 * w - 1 + dx < 128);
            if (inb) {
#pragma unroll
                for (int tt = 0; tt < 14; tt++) lg[tt] += BT[tap * 32 + 14 * ksub + tt];
            }
        }
        if (ksub) { lg[11] = -1e30f; lg[12] = -1e30f; lg[13] = -1e30f; }
        float mx = lg[0];
#pragma unroll
        for (int tt = 1; tt < 14; tt++) mx = fmaxf(mx, lg[tt]);
        mx = fmaxf(mx, __shfl_xor_sync(0xffffffffu, mx, 16));
        float sum = 0.f;
#pragma unroll
        for (int tt = 0; tt < 14; tt++) { lg[tt] = __expf(lg[tt] - mx); sum += lg[tt]; }
        sum += __shfl_xor_sync(0xffffffffu, sum, 16);
        float inv = 1.f / sum;
#pragma unroll
        for (int tt = 0; tt < 14; tt++) {
            int k = 14 * ksub + tt;
            if (k < 25)
                g_mask[((b * 25 + k) << 12) + (h << 6) + w] = lg[tt] * inv;
        }
    }
}

// ============================================================================
// Kernel 3: 25-tap s2 weighted gather. 256 blocks, 128 threads, 1 px/thread.
// Spatial-pair f32x2, 4-stage cp.async, one barrier per iteration.
// ============================================================================
__global__ __launch_bounds__(128) void aggregate_kernel(const float* __restrict__ x,
                                                        float* __restrict__ out) {
    int bid = blockIdx.x;
    int b   = bid >> 5;
    int t   = bid & 31;
    int w0 = (t & 3) * 16;
    int h0 = (t >> 2) * 8;
    int tid = threadIdx.x;
    int px = tid & 15;
    int py = tid >> 4;          // 0..7
    int h = h0 + py, w = w0 + px;

    __shared__ __align__(16) float AS[4 * A_STGF];

    for (int i = tid; i < 4 * A_STGF; i += 128) AS[i] = 0.f;

    int goff[3]; bool vld[3]; uint32_t soff[3];
#pragma unroll
    for (int j = 0; j < 3; j++) {
        int idx = tid + j * 128;
        bool ok = idx < A_CHUNK;
        int pl = 0, r = 0, q = 0, row = 0, col = 0;
        if (ok) {
            pl = idx / 190; int rem = idx - pl * 190;
            r = rem / 10; q = rem - r * 10;
            row = 2 * h0 - 2 + r;
            col = 2 * w0 - 4 + 4 * q;
            ok = (row >= 0) && (row < 128) && (col >= 0) && (col <= 124);
        }
        vld[j]  = ok;
        goff[j] = ok ? (pl * 16384 + (row << 7) + col) : 0;
        soff[j] = ok ? (uint32_t)((pl * A_CHF + r * A_RFLT + 4 * q) * 4) : 0u;
    }
    uint32_t asa = smem_u32(AS);
    const float* xb = x + (size_t)b * 256 * 16384;

    // masks -> packed spatial pairs
    ull mp[5][3];
    {
        float m[25];
#pragma unroll
        for (int k = 0; k < 25; k++)
            m[k] = g_mask[((b * 25 + k) << 12) + (h << 6) + w];
#pragma unroll
        for (int di = 0; di < 5; di++) {
            mp[di][0] = pack2(m[5 * di],     m[5 * di + 1]);
            mp[di][1] = pack2(m[5 * di + 2], m[5 * di + 3]);
            mp[di][2] = pack2(m[5 * di + 4], 0.f);
        }
    }

    auto fill = [&](int s, int cp) {
        const float* xc = xb + (size_t)(2 * cp) * 16384;
        uint32_t base = asa + (uint32_t)s * (A_STGF * 4);
#pragma unroll
        for (int j = 0; j < 3; j++)
            if (vld[j]) cpa16(base + soff[j], xc + goff[j]);
    };

    float* ob = out + (((size_t)b * 256) << 12) + (h << 6) + w;
    __syncthreads();
    fill(0, 0); CP_COMMIT();
    fill(1, 1); CP_COMMIT();

#pragma unroll 1
    for (int i = 0; i < 128; i++) {
        if (i + 2 < 128) fill((i + 2) & 3, i + 2);
        CP_COMMIT();
        cp_wait<2>();
        __syncthreads();

        const float* rp = AS + (i & 3) * A_STGF;
        ull accA = 0ull, accB = 0ull;
#pragma unroll
        for (int di = 0; di < 5; di++) {
            const float* rr = rp + (2 * py + di) * A_RFLT + 2 * px + 2;
            ull x0 = *(const ull*)(rr);
            ull x1 = *(const ull*)(rr + 2);
            ull x2 = *(const ull*)(rr + 4);
            FMA2(accA, mp[di][0], x0);
            FMA2(accA, mp[di][1], x1);
            FMA2(accA, mp[di][2], x2);
            const float* rr2 = rr + A_CHF;
            ull y0 = *(const ull*)(rr2);
            ull y1 = *(const ull*)(rr2 + 2);
            ull y2 = *(const ull*)(rr2 + 4);
            FMA2(accB, mp[di][0], y0);
            FMA2(accB, mp[di][1], y1);
            FMA2(accB, mp[di][2], y2);
        }
        float a0, a1, b0, b1;
        unpack2(accA, a0, a1);
        unpack2(accB, b0, b1);
        ob[((size_t)(2 * i)) << 12]     = a0 + a1;
        ob[((size_t)(2 * i + 1)) << 12] = b0 + b1;
    }
}

// ============================================================================
extern "C" void kernel_launch(void* const* d_in, const int* in_sizes, int n_in,
                              void* d_out, int out_size) {
    const float* x       = (const float*)d_in[0];
    const float* w_comp  = (const float*)d_in[1];
    const float* b_comp  = (const float*)d_in[2];
    const float* w_enc   = (const float*)d_in[3];
    const float* b_enc   = (const float*)d_in[4];
    const float* power_p = (const float*)d_in[5];
    float* out = (float*)d_out;

    prep_kernel<<<25, 256>>>(w_comp, b_comp, w_enc, b_enc, power_p);
    logits_kernel<<<256, 128>>>(x);
    aggregate_kernel<<<256, 128>>>(x, out);
}

// round 9
// speedup vs baseline: 1.9248x; 1.4773x over previous
#include <cuda_runtime.h>
#include <cstdint>

typedef unsigned long long ull;

// Problem: x (8,256,128,128) f32 -> out (8,256,64,64) f32
// CARAFE downsample, decomposed:
//   compress: cx[b,h,w,cc] = sum_c x[b,c,h,w]*w_comp[cc,c] + b_comp   (tf32 mma GEMM)
//   encoder:  logit[k]     = 3x3-s2 conv(cx) * exp(p)                 (tf32 mma GEMM, K=576)
//   softmax -> masks; aggregate: 25-tap s2 gather of x                (f32x2 scalar)

// ---------------- compress geometry ----------------
#define C_XP    132                  // x stage pitch (floats per c-row)
#define C_XSF   4224                 // 32*132
#define C_WBP   36
#define C_WBSF  2304                 // 64*36
#define C_SMEMF (4*C_XSF + 4*C_WBSF + 64)
// ---------------- encoder geometry ----------------
#define E_CXP   68                   // px-slot pitch (floats)
#define E_SLOTS 297                  // 9 rows * 33 cols
#define E_CXSF  (E_SLOTS * E_CXP)    // 20196
#define E_WEP   580
#define E_WESF  (32 * E_WEP)         // 18560
#define E_SMEMF (E_CXSF + E_WESF + 32)
// ---------------- aggregate geometry ----------------
#define A_CHF   760                  // 19 rows * 40 floats
#define A_STGF  3040                 // 4 channels per stage
#define A_NCHUNK 760

// ---- persistent device scratch ----
__device__ float g_wb[64 * 256];         // tf32-rounded w_comp [cc][c]
__device__ float g_web[32 * 576];        // tf32-rounded w_enc*expP, [n=k_out][k=tap*64+cc]
__device__ float g_bk[32];               // b_enc * expP
__device__ float g_bc[64];               // b_comp
__device__ float g_mask[8 * 25 * 4096];  // softmaxed masks [b][k][h][w]
__device__ float g_cx[8 * 128 * 128 * 64];  // compressed features, px-major [b][h][w][cc]

__device__ __forceinline__ ull pack2(float a, float b) {
    ull r; asm("mov.b64 %0, {%1, %2};" : "=l"(r) : "f"(a), "f"(b)); return r;
}
__device__ __forceinline__ void unpack2(ull v, float& a, float& b) {
    asm("mov.b64 {%0, %1}, %2;" : "=f"(a), "=f"(b) : "l"(v));
}
#define FMA2(d, a, b) asm("fma.rn.f32x2 %0, %1, %2, %0;" : "+l"(d) : "l"(a), "l"(b))

__device__ __forceinline__ uint32_t f2tf(float f) {
    uint32_t r; asm("cvt.rna.tf32.f32 %0, %1;" : "=r"(r) : "f"(f)); return r;
}
__device__ __forceinline__ void mma_tf32(float* d, const uint32_t* a, uint32_t b0, uint32_t b1) {
    asm volatile("mma.sync.aligned.m16n8k8.row.col.f32.tf32.tf32.f32 "
                 "{%0,%1,%2,%3}, {%4,%5,%6,%7}, {%8,%9}, {%0,%1,%2,%3};"
                 : "+f"(d[0]), "+f"(d[1]), "+f"(d[2]), "+f"(d[3])
                 : "r"(a[0]), "r"(a[1]), "r"(a[2]), "r"(a[3]), "r"(b0), "r"(b1));
}

__device__ __forceinline__ uint32_t smem_u32(const void* p) {
    return (uint32_t)__cvta_generic_to_shared(p);
}
__device__ __forceinline__ void cpa16(uint32_t dst, const void* src) {
    asm volatile("cp.async.ca.shared.global [%0], [%1], 16;" :: "r"(dst), "l"(src));
}
#define CP_COMMIT() asm volatile("cp.async.commit_group;")
template<int N> __device__ __forceinline__ void cp_wait() {
    asm volatile("cp.async.wait_group %0;" :: "n"(N));
}

// ============================================================================
// Kernel 1: prep. 96 blocks x 256 threads.
//  blocks 0..63: wb row cc; blocks 64..95: web row n (+bk, bc on 64/65).
// ============================================================================
__global__ void prep_kernel(const float* __restrict__ w_comp, const float* __restrict__ b_comp,
                            const float* __restrict__ w_enc, const float* __restrict__ b_enc,
                            const float* __restrict__ power_p) {
    int bid = blockIdx.x, t = threadIdx.x;
    float expP = __expf(power_p[0]);
    if (bid < 64) {
        g_wb[bid * 256 + t] = __uint_as_float(f2tf(w_comp[bid * 256 + t]));
    } else {
        int n = bid - 64;
        for (int i = t; i < 576; i += 256) {
            float v = 0.f;
            if (n < 25) {
                int cc = i & 63, tap = i >> 6;
                v = w_enc[((n * 64 + cc) * 9) + tap] * expP;
            }
            g_web[n * 576 + i] = __uint_as_float(f2tf(v));
        }
        if (n == 0 && t < 32) g_bk[t] = (t < 25) ? b_enc[t] * expP : 0.f;
        if (n == 1 && t < 64) g_bc[t] = b_comp[t];
    }
}

// ============================================================================
// Kernel 2: compress GEMM. 1024 blocks (b*128+h), 128 threads (4 warps).
// M=128 (w), N=64 (cc), K=256 (c); tf32 m16n8k8; 4-stage cp.async over 8
// K-chunks of 32 channels. Output cx px-major + b_comp.
// ============================================================================
__global__ __launch_bounds__(128) void compress_kernel(const float* __restrict__ x) {
    extern __shared__ __align__(16) float SM[];
    int bid = blockIdx.x;
    int b = bid >> 7, h = bid & 127;
    int tid = threadIdx.x;
    int wid = tid >> 5, lane = tid & 31;
    int g = lane >> 2, tig = lane & 3;

    float* XS = SM;                        // 4 stages of [32 c][132]
    float* WBS = SM + 4 * C_XSF;           // 4 stages of [64 cc][36]
    float* BC  = SM + 4 * C_XSF + 4 * C_WBSF;

    if (tid < 64) BC[tid] = g_bc[tid];

    uint32_t xsa = smem_u32(XS), wba = smem_u32(WBS);
    const float* xb = x + ((size_t)b * 256) * 16384 + h * 128;

    auto fill = [&](int s, int kc) {       // kc: chunk of 32 channels
        const float* xc = xb + (size_t)(kc * 32) * 16384;
        uint32_t xd = xsa + (uint32_t)s * (C_XSF * 4);
#pragma unroll
        for (int j = 0; j < 8; j++) {
            int idx = tid + j * 128;
            int c = idx >> 5, q = idx & 31;
            cpa16(xd + (uint32_t)(c * C_XP + 4 * q) * 4, xc + (size_t)c * 16384 + 4 * q);
        }
        uint32_t wd = wba + (uint32_t)s * (C_WBSF * 4);
#pragma unroll
        for (int j = 0; j < 4; j++) {
            int idx = tid + j * 128;
            int cc = idx >> 3, q = idx & 7;
            cpa16(wd + (uint32_t)(cc * C_WBP + 4 * q) * 4, g_wb + cc * 256 + kc * 32 + 4 * q);
        }
    };

    float d[2][8][4];
#pragma unroll
    for (int mt = 0; mt < 2; mt++)
#pragma unroll
        for (int nt = 0; nt < 8; nt++)
#pragma unroll
            for (int j = 0; j < 4; j++) d[mt][nt][j] = 0.f;

    fill(0, 0); CP_COMMIT();
    fill(1, 1); CP_COMMIT();
#pragma unroll 1
    for (int i = 0; i < 8; i++) {
        if (i + 2 < 8) fill((i + 2) & 3, i + 2);
        CP_COMMIT();
        cp_wait<2>();
        __syncthreads();

        const float* xs = XS + (i & 3) * C_XSF;
        const uint32_t* wbs = (const uint32_t*)(WBS + (i & 3) * C_WBSF);
#pragma unroll
        for (int k8 = 0; k8 < 4; k8++) {
            int cb = k8 * 8;
            uint32_t a[2][4];
#pragma unroll
            for (int mt = 0; mt < 2; mt++) {
                int pxl = 32 * wid + 16 * mt + g;
                a[mt][0] = f2tf(xs[(cb + tig) * C_XP + pxl]);
                a[mt][1] = f2tf(xs[(cb + tig) * C_XP + pxl + 8]);
                a[mt][2] = f2tf(xs[(cb + tig + 4) * C_XP + pxl]);
                a[mt][3] = f2tf(xs[(cb + tig + 4) * C_XP + pxl + 8]);
            }
#pragma unroll
            for (int nt = 0; nt < 8; nt++) {
                uint32_t b0 = wbs[(8 * nt + g) * C_WBP + cb + tig];
                uint32_t b1 = wbs[(8 * nt + g) * C_WBP + cb + tig + 4];
                mma_tf32(d[0][nt], a[0], b0, b1);
                mma_tf32(d[1][nt], a[1], b0, b1);
            }
        }
    }

    // epilogue: + b_comp, store px-major cx
    size_t base = (size_t)bid * 128 * 64;
#pragma unroll
    for (int mt = 0; mt < 2; mt++) {
#pragma unroll
        for (int nt = 0; nt < 8; nt++) {
            int pxl = 32 * wid + 16 * mt + g;
            int cc = 8 * nt + 2 * tig;
            float bc0 = BC[cc], bc1 = BC[cc + 1];
            float2 v0 = make_float2(d[mt][nt][0] + bc0, d[mt][nt][1] + bc1);
            float2 v1 = make_float2(d[mt][nt][2] + bc0, d[mt][nt][3] + bc1);
            *(float2*)&g_cx[base + (size_t)pxl * 64 + cc] = v0;
            *(float2*)&g_cx[base + (size_t)(pxl + 8) * 64 + cc] = v1;
        }
    }
}

// ============================================================================
// Kernel 3: encoder GEMM + softmax -> g_mask. 512 blocks (8b x 64 tiles of
// 16w x 4h), 128 threads. M=64 px, N=32 (25 k padded), K=576 (tap*64+cc).
// cx patch staged once (zero-padded borders), tf32 m16n8k8, warp=m-tile.
// ============================================================================
__global__ __launch_bounds__(128) void encoder_kernel() {
    extern __shared__ __align__(16) float SM[];
    int bid = blockIdx.x;
    int b = bid >> 6, t = bid & 63;
    int w0 = (t & 3) * 16;
    int h0 = (t >> 2) * 4;
    int tid = threadIdx.x;
    int wid = tid >> 5, lane = tid & 31;
    int g = lane >> 2, tig = lane & 3;

    float* CXS = SM;
    float* WES = SM + E_CXSF;
    float* BKS = SM + E_CXSF + E_WESF;

    // zero cx stage (borders stay zero)
    float4 z4 = make_float4(0.f, 0.f, 0.f, 0.f);
    for (int i = tid; i < E_CXSF / 4; i += 128) ((float4*)CXS)[i] = z4;
    if (tid < 32) BKS[tid] = g_bk[tid];
    __syncthreads();

    uint32_t cxa = smem_u32(CXS), wea = smem_u32(WES);
    // we: 4608 chunks
#pragma unroll 4
    for (int j = 0; j < 36; j++) {
        int idx = tid + j * 128;
        int n = idx / 144, q = idx - n * 144;
        cpa16(wea + (uint32_t)(n * E_WEP + 4 * q) * 4, g_web + n * 576 + 4 * q);
    }
    // cx patch: 9 rows x 33 px x 64 cc -> 4752 chunks
#pragma unroll 4
    for (int j = 0; j < 38; j++) {
        int idx = tid + j * 128;
        if (idx < 4752) {
            int r = idx / 528; int rem = idx - r * 528;
            int pi = rem >> 4, q = rem & 15;
            int hr = 2 * h0 - 1 + r;
            int wc = 2 * w0 - 1 + pi;
            if (hr >= 0 && hr < 128 && wc >= 0 && wc < 128)
                cpa16(cxa + (uint32_t)((r * 33 + pi) * E_CXP + 4 * q) * 4,
                      g_cx + ((size_t)(b * 128 + hr) * 128 + wc) * 64 + 4 * q);
        }
    }
    CP_COMMIT();
    cp_wait<0>();
    __syncthreads();

    float d[4][4];
#pragma unroll
    for (int nt = 0; nt < 4; nt++)
#pragma unroll
        for (int j = 0; j < 4; j++) d[nt][j] = 0.f;

    const uint32_t* weu = (const uint32_t*)WES;
#pragma unroll 1
    for (int tap = 0; tap < 9; tap++) {
        int dy = tap / 3, dx = tap % 3;
        const float* baseL = CXS + ((2 * wid + dy) * 33 + (2 * g + dx)) * E_CXP;
        const float* baseH = baseL + 16 * E_CXP;
#pragma unroll
        for (int kc = 0; kc < 8; kc++) {
            int cb = kc * 8;
            uint32_t a[4];
            a[0] = f2tf(baseL[cb + tig]);
            a[1] = f2tf(baseH[cb + tig]);
            a[2] = f2tf(baseL[cb + tig + 4]);
            a[3] = f2tf(baseH[cb + tig + 4]);
            int ko = tap * 64 + cb + tig;
#pragma unroll
            for (int nt = 0; nt < 4; nt++) {
                uint32_t b0 = weu[(8 * nt + g) * E_WEP + ko];
                uint32_t b1 = weu[(8 * nt + g) * E_WEP + ko + 4];
                mma_tf32(d[nt], a, b0, b1);
            }
        }
    }

    // softmax per row (rows: px = 16*wid+g and +8; h = h0+wid)
    int hh = h0 + wid;
#pragma unroll
    for (int half = 0; half < 2; half++) {
        int ww = w0 + g + 8 * half;
        float lg[8];
#pragma unroll
        for (int nt = 0; nt < 4; nt++) {
#pragma unroll
            for (int j = 0; j < 2; j++) {
                int n = 8 * nt + 2 * tig + j;
                float v = d[nt][2 * half + j];
                lg[nt * 2 + j] = (n < 25) ? (v + BKS[n]) : -1e30f;
            }
        }
        float mx = lg[0];
#pragma unroll
        for (int j = 1; j < 8; j++) mx = fmaxf(mx, lg[j]);
        mx = fmaxf(mx, __shfl_xor_sync(0xffffffffu, mx, 1));
        mx = fmaxf(mx, __shfl_xor_sync(0xffffffffu, mx, 2));
        float sum = 0.f;
#pragma unroll
        for (int j = 0; j < 8; j++) { lg[j] = __expf(lg[j] - mx); sum += lg[j]; }
        sum += __shfl_xor_sync(0xffffffffu, sum, 1);
        sum += __shfl_xor_sync(0xffffffffu, sum, 2);
        float inv = 1.f / sum;
#pragma unroll
        for (int nt = 0; nt < 4; nt++) {
#pragma unroll
            for (int j = 0; j < 2; j++) {
                int n = 8 * nt + 2 * tig + j;
                if (n < 25)
                    g_mask[((b * 25 + n) << 12) + (hh << 6) + ww] = lg[nt * 2 + j] * inv;
            }
        }
    }
}

// ============================================================================
// Kernel 4: 25-tap s2 weighted gather. 256 blocks (8b x 32 tiles of 16w x 8h),
// 128 threads. Lane map: px(16) x ccsel(2); warp = py2; thread covers
// py2 & py2+4, cc pair -> every LDS.64 is 2 clean wavefronts.
// 4 channels/stage, 64 iters, 4-stage cp.async, one barrier/iter.
// ============================================================================
__global__ __launch_bounds__(128) void aggregate_kernel(const float* __restrict__ x,
                                                        float* __restrict__ out) {
    int bid = blockIdx.x;
    int b = bid >> 5;
    int t = bid & 31;
    int w0 = (t & 3) * 16;
    int h0 = (t >> 2) * 8;
    int tid = threadIdx.x;
    int px  = tid & 15;
    int ccs = (tid >> 4) & 1;
    int py2 = tid >> 5;               // 0..3 (= warp id)
    int w = w0 + px;

    __shared__ __align__(16) float AS[4 * A_STGF];
    for (int i = tid; i < 4 * A_STGF; i += 128) AS[i] = 0.f;

    uint32_t asa = smem_u32(AS);
    const float* xb = x + (size_t)b * 256 * 16384;

    // masks for both rows (py2, py2+4) packed as spatial pairs
    ull mp[2][5][3];
#pragma unroll
    for (int pyi = 0; pyi < 2; pyi++) {
        int h = h0 + py2 + 4 * pyi;
        float m[25];
#pragma unroll
        for (int k = 0; k < 25; k++)
            m[k] = g_mask[((b * 25 + k) << 12) + (h << 6) + w];
#pragma unroll
        for (int di = 0; di < 5; di++) {
            mp[pyi][di][0] = pack2(m[5 * di],     m[5 * di + 1]);
            mp[pyi][di][1] = pack2(m[5 * di + 2], m[5 * di + 3]);
            mp[pyi][di][2] = pack2(m[5 * di + 4], 0.f);
        }
    }

    auto fill = [&](int s, int ci) {      // ci: channel group of 4
        const float* xc = xb + (size_t)(4 * ci) * 16384;
        uint32_t base = asa + (uint32_t)s * (A_STGF * 4);
#pragma unroll
        for (int j = 0; j < 6; j++) {
            int idx = tid + j * 128;
            if (idx < A_NCHUNK) {
                int ch = idx / 190; int rem = idx - ch * 190;
                int r = rem / 10;   int q = rem - r * 10;
                int row = 2 * h0 - 2 + r;
                int col = 2 * w0 - 4 + 4 * q;
                if (row >= 0 && row < 128 && col >= 0 && col <= 124)
                    cpa16(base + (uint32_t)idx * 16, xc + ch * 16384 + (row << 7) + col);
            }
        }
    };

    float* ob = out + (((size_t)b * 256) << 12) + w;
    __syncthreads();
    fill(0, 0); CP_COMMIT();
    fill(1, 1); CP_COMMIT();

#pragma unroll 1
    for (int i = 0; i < 64; i++) {
        if (i + 2 < 64) fill((i + 2) & 3, i + 2);
        CP_COMMIT();
        cp_wait<2>();
        __syncthreads();

        const float* rp = AS + (i & 3) * A_STGF;
#pragma unroll
        for (int pyi = 0; pyi < 2; pyi++) {
            int py = py2 + 4 * pyi;
#pragma unroll
            for (int c2 = 0; c2 < 2; c2++) {
                int cc = 2 * ccs + c2;
                ull acc = 0ull;
                const float* cpp = rp + cc * A_CHF + 2 * px + 2;
#pragma unroll
                for (int di = 0; di < 5; di++) {
                    const float* rr = cpp + (2 * py + di) * 40;
                    FMA2(acc, mp[pyi][di][0], *(const ull*)(rr));
                    FMA2(acc, mp[pyi][di][1], *(const ull*)(rr + 2));
                    FMA2(acc, mp[pyi][di][2], *(const ull*)(rr + 4));
                }
                float a0, a1;
                unpack2(acc, a0, a1);
                ob[((size_t)(4 * i + cc) << 12) + ((h0 + py) << 6)] = a0 + a1;
            }
        }
    }
}

// ============================================================================
extern "C" void kernel_launch(void* const* d_in, const int* in_sizes, int n_in,
                              void* d_out, int out_size) {
    const float* x       = (const float*)d_in[0];
    const float* w_comp  = (const float*)d_in[1];
    const float* b_comp  = (const float*)d_in[2];
    const float* w_enc   = (const float*)d_in[3];
    const float* b_enc   = (const float*)d_in[4];
    const float* power_p = (const float*)d_in[5];
    float* out = (float*)d_out;

    cudaFuncSetAttribute(compress_kernel, cudaFuncAttributeMaxDynamicSharedMemorySize,
                         C_SMEMF * 4);
    cudaFuncSetAttribute(encoder_kernel, cudaFuncAttributeMaxDynamicSharedMemorySize,
                         E_SMEMF * 4);

    prep_kernel<<<96, 256>>>(w_comp, b_comp, w_enc, b_enc, power_p);
    compress_kernel<<<1024, 128, C_SMEMF * 4>>>(x);
    encoder_kernel<<<512, 128, E_SMEMF * 4>>>();
    aggregate_kernel<<<256, 128>>>(x, out);
}

// round 10
// speedup vs baseline: 1.9743x; 1.0257x over previous
#include <cuda_runtime.h>
#include <cstdint>

typedef unsigned long long ull;

// Problem: x (8,256,128,128) f32 -> out (8,256,64,64) f32
// CARAFE downsample, decomposed:
//   compress: cx[b,h,w,cc] = sum_c x[b,c,h,w]*w_comp[cc,c] + b_comp   (tf32 mma GEMM)
//   encoder:  logit[k]     = 3x3-s2 conv(cx) * exp(p)                 (tf32 mma GEMM, K=576)
//   softmax -> masks; aggregate: 25-tap s2 gather of x                (f32x2 scalar)

// ---------------- compress geometry (M=256: 2 rows/block) ----------------
#define C_XP    264                  // x stage pitch (floats per c-row; 264%32=8 -> bank-exact)
#define C_XSF   8448                 // 32*264
#define C_WBP   36
#define C_WBSF  2304                 // 64*36
#define C_SMEMF (4*C_XSF + 4*C_WBSF + 64)
// ---------------- encoder geometry ----------------
#define E_CXP   68
#define E_SLOTS 297                  // 9 rows * 33 cols
#define E_CXSF  (E_SLOTS * E_CXP)    // 20196
#define E_WEP   580
#define E_WESF  (32 * E_WEP)         // 18560
#define E_SMEMF (E_CXSF + E_WESF + 32)
// ---------------- aggregate geometry (8 ch/stage) ----------------
#define A_CHF   760                  // 19 rows * 40 floats
#define A_STGF  6080                 // 8 channels per stage
#define A_NCHUNK 1520
#define A_SMEMF (4 * A_STGF)

// ---- persistent device scratch ----
__device__ float g_wb[64 * 256];         // tf32-rounded w_comp [cc][c]
__device__ float g_web[32 * 576];        // tf32-rounded w_enc*expP, [n][tap*64+cc]
__device__ float g_bk[32];               // b_enc * expP
__device__ float g_bc[64];               // b_comp
__device__ float g_mask[8 * 25 * 4096];  // softmaxed masks [b][k][h][w]
__device__ float g_cx[8 * 128 * 128 * 64];  // compressed features, px-major [b][h][w][cc]

__device__ __forceinline__ ull pack2(float a, float b) {
    ull r; asm("mov.b64 %0, {%1, %2};" : "=l"(r) : "f"(a), "f"(b)); return r;
}
__device__ __forceinline__ void unpack2(ull v, float& a, float& b) {
    asm("mov.b64 {%0, %1}, %2;" : "=f"(a), "=f"(b) : "l"(v));
}
#define FMA2(d, a, b) asm("fma.rn.f32x2 %0, %1, %2, %0;" : "+l"(d) : "l"(a), "l"(b))

__device__ __forceinline__ uint32_t f2tf(float f) {
    uint32_t r; asm("cvt.rna.tf32.f32 %0, %1;" : "=r"(r) : "f"(f)); return r;
}
__device__ __forceinline__ void mma_tf32(float* d, const uint32_t* a, uint32_t b0, uint32_t b1) {
    asm volatile("mma.sync.aligned.m16n8k8.row.col.f32.tf32.tf32.f32 "
                 "{%0,%1,%2,%3}, {%4,%5,%6,%7}, {%8,%9}, {%0,%1,%2,%3};"
                 : "+f"(d[0]), "+f"(d[1]), "+f"(d[2]), "+f"(d[3])
                 : "r"(a[0]), "r"(a[1]), "r"(a[2]), "r"(a[3]), "r"(b0), "r"(b1));
}

__device__ __forceinline__ uint32_t smem_u32(const void* p) {
    return (uint32_t)__cvta_generic_to_shared(p);
}
__device__ __forceinline__ void cpa16(uint32_t dst, const void* src) {
    asm volatile("cp.async.ca.shared.global [%0], [%1], 16;" :: "r"(dst), "l"(src));
}
#define CP_COMMIT() asm volatile("cp.async.commit_group;")
template<int N> __device__ __forceinline__ void cp_wait() {
    asm volatile("cp.async.wait_group %0;" :: "n"(N));
}

// ============================================================================
// Kernel 1: prep. 96 blocks x 256 threads.
// ============================================================================
__global__ void prep_kernel(const float* __restrict__ w_comp, const float* __restrict__ b_comp,
                            const float* __restrict__ w_enc, const float* __restrict__ b_enc,
                            const float* __restrict__ power_p) {
    int bid = blockIdx.x, t = threadIdx.x;
    float expP = __expf(power_p[0]);
    if (bid < 64) {
        g_wb[bid * 256 + t] = __uint_as_float(f2tf(w_comp[bid * 256 + t]));
    } else {
        int n = bid - 64;
        for (int i = t; i < 576; i += 256) {
            float v = 0.f;
            if (n < 25) {
                int cc = i & 63, tap = i >> 6;
                v = w_enc[((n * 64 + cc) * 9) + tap] * expP;
            }
            g_web[n * 576 + i] = __uint_as_float(f2tf(v));
        }
        if (n == 0 && t < 32) g_bk[t] = (t < 25) ? b_enc[t] * expP : 0.f;
        if (n == 1 && t < 64) g_bc[t] = b_comp[t];
    }
}

// ============================================================================
// Kernel 2: compress GEMM. 512 blocks (b*64+h2, 2 rows each), 256 threads.
// M=256 (2 rows x 128 w), N=64 (cc), K=256 (c); tf32 m16n8k8;
// 4-stage cp.async over 8 K-chunks of 32 channels. Output cx px-major.
// ============================================================================
__global__ __launch_bounds__(256) void compress_kernel(const float* __restrict__ x) {
    extern __shared__ __align__(16) float SM[];
    int bid = blockIdx.x;
    int b = bid >> 6, h2 = bid & 63;
    int tid = threadIdx.x;
    int wid = tid >> 5, lane = tid & 31;
    int g = lane >> 2, tig = lane & 3;

    float* XS  = SM;                         // 4 stages of [32 c][264]
    float* WBS = SM + 4 * C_XSF;             // 4 stages of [64 cc][36]
    float* BC  = SM + 4 * C_XSF + 4 * C_WBSF;

    if (tid < 64) BC[tid] = g_bc[tid];

    uint32_t xsa = smem_u32(XS), wba = smem_u32(WBS);
    const float* xb = x + ((size_t)b * 256) * 16384 + h2 * 256;   // 2 rows = 256 contiguous

    auto fill = [&](int s, int kc) {         // kc: chunk of 32 channels
        const float* xc = xb + (size_t)(kc * 32) * 16384;
        uint32_t xd = xsa + (uint32_t)s * (C_XSF * 4);
#pragma unroll
        for (int j = 0; j < 8; j++) {
            int idx = tid + j * 256;
            int c = idx >> 6, q = idx & 63;
            cpa16(xd + (uint32_t)(c * C_XP + 4 * q) * 4, xc + (size_t)c * 16384 + 4 * q);
        }
        uint32_t wd = wba + (uint32_t)s * (C_WBSF * 4);
#pragma unroll
        for (int j = 0; j < 2; j++) {
            int idx = tid + j * 256;
            int cc = idx >> 3, q = idx & 7;
            cpa16(wd + (uint32_t)(cc * C_WBP + 4 * q) * 4, g_wb + cc * 256 + kc * 32 + 4 * q);
        }
    };

    float d[2][8][4];
#pragma unroll
    for (int mt = 0; mt < 2; mt++)
#pragma unroll
        for (int nt = 0; nt < 8; nt++)
#pragma unroll
            for (int j = 0; j < 4; j++) d[mt][nt][j] = 0.f;

    fill(0, 0); CP_COMMIT();
    fill(1, 1); CP_COMMIT();
#pragma unroll 1
    for (int i = 0; i < 8; i++) {
        if (i + 2 < 8) fill((i + 2) & 3, i + 2);
        CP_COMMIT();
        cp_wait<2>();
        __syncthreads();

        const float* xs = XS + (i & 3) * C_XSF;
        const uint32_t* wbs = (const uint32_t*)(WBS + (i & 3) * C_WBSF);
#pragma unroll
        for (int k8 = 0; k8 < 4; k8++) {
            int cb = k8 * 8;
            uint32_t a[2][4];
#pragma unroll
            for (int mt = 0; mt < 2; mt++) {
                int pxl = 32 * wid + 16 * mt + g;
                a[mt][0] = f2tf(xs[(cb + tig) * C_XP + pxl]);
                a[mt][1] = f2tf(xs[(cb + tig) * C_XP + pxl + 8]);
                a[mt][2] = f2tf(xs[(cb + tig + 4) * C_XP + pxl]);
                a[mt][3] = f2tf(xs[(cb + tig + 4) * C_XP + pxl + 8]);
            }
#pragma unroll
            for (int nt = 0; nt < 8; nt++) {
                uint32_t b0 = wbs[(8 * nt + g) * C_WBP + cb + tig];
                uint32_t b1 = wbs[(8 * nt + g) * C_WBP + cb + tig + 4];
                mma_tf32(d[0][nt], a[0], b0, b1);
                mma_tf32(d[1][nt], a[1], b0, b1);
            }
        }
    }

    size_t base = (size_t)bid * 256 * 64;
#pragma unroll
    for (int mt = 0; mt < 2; mt++) {
#pragma unroll
        for (int nt = 0; nt < 8; nt++) {
            int pxl = 32 * wid + 16 * mt + g;
            int cc = 8 * nt + 2 * tig;
            float bc0 = BC[cc], bc1 = BC[cc + 1];
            float2 v0 = make_float2(d[mt][nt][0] + bc0, d[mt][nt][1] + bc1);
            float2 v1 = make_float2(d[mt][nt][2] + bc0, d[mt][nt][3] + bc1);
            *(float2*)&g_cx[base + (size_t)pxl * 64 + cc] = v0;
            *(float2*)&g_cx[base + (size_t)(pxl + 8) * 64 + cc] = v1;
        }
    }
}

// ============================================================================
// Kernel 3: encoder GEMM + softmax -> g_mask. 512 blocks (8b x 64 tiles of
// 16w x 4h), 128 threads. M=64 px, N=32 (25 k padded), K=576 (tap*64+cc).
// ============================================================================
__global__ __launch_bounds__(128) void encoder_kernel() {
    extern __shared__ __align__(16) float SM[];
    int bid = blockIdx.x;
    int b = bid >> 6, t = bid & 63;
    int w0 = (t & 3) * 16;
    int h0 = (t >> 2) * 4;
    int tid = threadIdx.x;
    int wid = tid >> 5, lane = tid & 31;
    int g = lane >> 2, tig = lane & 3;

    float* CXS = SM;
    float* WES = SM + E_CXSF;
    float* BKS = SM + E_CXSF + E_WESF;

    float4 z4 = make_float4(0.f, 0.f, 0.f, 0.f);
    for (int i = tid; i < E_CXSF / 4; i += 128) ((float4*)CXS)[i] = z4;
    if (tid < 32) BKS[tid] = g_bk[tid];
    __syncthreads();

    uint32_t cxa = smem_u32(CXS), wea = smem_u32(WES);
#pragma unroll 4
    for (int j = 0; j < 36; j++) {
        int idx = tid + j * 128;
        int n = idx / 144, q = idx - n * 144;
        cpa16(wea + (uint32_t)(n * E_WEP + 4 * q) * 4, g_web + n * 576 + 4 * q);
    }
#pragma unroll 4
    for (int j = 0; j < 38; j++) {
        int idx = tid + j * 128;
        if (idx < 4752) {
            int r = idx / 528; int rem = idx - r * 528;
            int pi = rem >> 4, q = rem & 15;
            int hr = 2 * h0 - 1 + r;
            int wc = 2 * w0 - 1 + pi;
            if (hr >= 0 && hr < 128 && wc >= 0 && wc < 128)
                cpa16(cxa + (uint32_t)((r * 33 + pi) * E_CXP + 4 * q) * 4,
                      g_cx + ((size_t)(b * 128 + hr) * 128 + wc) * 64 + 4 * q);
        }
    }
    CP_COMMIT();
    cp_wait<0>();
    __syncthreads();

    float d[4][4];
#pragma unroll
    for (int nt = 0; nt < 4; nt++)
#pragma unroll
        for (int j = 0; j < 4; j++) d[nt][j] = 0.f;

    const uint32_t* weu = (const uint32_t*)WES;
#pragma unroll 1
    for (int tap = 0; tap < 9; tap++) {
        int dy = tap / 3, dx = tap % 3;
        const float* baseL = CXS + ((2 * wid + dy) * 33 + (2 * g + dx)) * E_CXP;
        const float* baseH = baseL + 16 * E_CXP;
#pragma unroll
        for (int kc = 0; kc < 8; kc++) {
            int cb = kc * 8;
            uint32_t a[4];
            a[0] = f2tf(baseL[cb + tig]);
            a[1] = f2tf(baseH[cb + tig]);
            a[2] = f2tf(baseL[cb + tig + 4]);
            a[3] = f2tf(baseH[cb + tig + 4]);
            int ko = tap * 64 + cb + tig;
#pragma unroll
            for (int nt = 0; nt < 4; nt++) {
                uint32_t b0 = weu[(8 * nt + g) * E_WEP + ko];
                uint32_t b1 = weu[(8 * nt + g) * E_WEP + ko + 4];
                mma_tf32(d[nt], a, b0, b1);
            }
        }
    }

    int hh = h0 + wid;
#pragma unroll
    for (int half = 0; half < 2; half++) {
        int ww = w0 + g + 8 * half;
        float lg[8];
#pragma unroll
        for (int nt = 0; nt < 4; nt++) {
#pragma unroll
            for (int j = 0; j < 2; j++) {
                int n = 8 * nt + 2 * tig + j;
                float v = d[nt][2 * half + j];
                lg[nt * 2 + j] = (n < 25) ? (v + BKS[n]) : -1e30f;
            }
        }
        float mx = lg[0];
#pragma unroll
        for (int j = 1; j < 8; j++) mx = fmaxf(mx, lg[j]);
        mx = fmaxf(mx, __shfl_xor_sync(0xffffffffu, mx, 1));
        mx = fmaxf(mx, __shfl_xor_sync(0xffffffffu, mx, 2));
        float sum = 0.f;
#pragma unroll
        for (int j = 0; j < 8; j++) { lg[j] = __expf(lg[j] - mx); sum += lg[j]; }
        sum += __shfl_xor_sync(0xffffffffu, sum, 1);
        sum += __shfl_xor_sync(0xffffffffu, sum, 2);
        float inv = 1.f / sum;
#pragma unroll
        for (int nt = 0; nt < 4; nt++) {
#pragma unroll
            for (int j = 0; j < 2; j++) {
                int n = 8 * nt + 2 * tig + j;
                if (n < 25)
                    g_mask[((b * 25 + n) << 12) + (hh << 6) + ww] = lg[nt * 2 + j] * inv;
            }
        }
    }
}

// ============================================================================
// Kernel 4: 25-tap s2 weighted gather. 256 blocks (8b x 32 tiles of 16w x 8h),
// 256 threads: px(16) x ccs(4) x py2(4... via tid>>6). 8 ch/stage, 32 iters,
// 4-stage cp.async, one barrier/iter.
// ============================================================================
__global__ __launch_bounds__(256) void aggregate_kernel(const float* __restrict__ x,
                                                        float* __restrict__ out) {
    extern __shared__ __align__(16) float AS[];
    int bid = blockIdx.x;
    int b = bid >> 5;
    int t = bid & 31;
    int w0 = (t & 3) * 16;
    int h0 = (t >> 2) * 8;
    int tid = threadIdx.x;
    int px  = tid & 15;
    int ccs = (tid >> 4) & 3;          // 2 channels each of 8/stage
    int py2 = tid >> 6;                // 0..3; rows py2 and py2+4
    int w = w0 + px;

    for (int i = tid; i < A_SMEMF; i += 256) AS[i] = 0.f;

    uint32_t asa = smem_u32(AS);
    const float* xb = x + (size_t)b * 256 * 16384;

    ull mp[2][5][3];
#pragma unroll
    for (int pyi = 0; pyi < 2; pyi++) {
        int h = h0 + py2 + 4 * pyi;
        float m[25];
#pragma unroll
        for (int k = 0; k < 25; k++)
            m[k] = g_mask[((b * 25 + k) << 12) + (h << 6) + w];
#pragma unroll
        for (int di = 0; di < 5; di++) {
            mp[pyi][di][0] = pack2(m[5 * di],     m[5 * di + 1]);
            mp[pyi][di][1] = pack2(m[5 * di + 2], m[5 * di + 3]);
            mp[pyi][di][2] = pack2(m[5 * di + 4], 0.f);
        }
    }

    auto fill = [&](int s, int ci) {      // ci: channel group of 8
        const float* xc = xb + (size_t)(8 * ci) * 16384;
        uint32_t base = asa + (uint32_t)s * (A_STGF * 4);
#pragma unroll
        for (int j = 0; j < 6; j++) {
            int idx = tid + j * 256;
            if (idx < A_NCHUNK) {
                int ch = idx / 190; int rem = idx - ch * 190;
                int r = rem / 10;   int q = rem - r * 10;
                int row = 2 * h0 - 2 + r;
                int col = 2 * w0 - 4 + 4 * q;
                if (row >= 0 && row < 128 && col >= 0 && col <= 124)
                    cpa16(base + (uint32_t)(ch * A_CHF + r * 40 + 4 * q) * 4,
                          xc + (size_t)ch * 16384 + (row << 7) + col);
            }
        }
    };

    float* ob = out + (((size_t)b * 256) << 12) + w;
    __syncthreads();
    fill(0, 0); CP_COMMIT();
    fill(1, 1); CP_COMMIT();

#pragma unroll 1
    for (int i = 0; i < 32; i++) {
        if (i + 2 < 32) fill((i + 2) & 3, i + 2);
        CP_COMMIT();
        cp_wait<2>();
        __syncthreads();

        const float* rp = AS + (i & 3) * A_STGF;
#pragma unroll
        for (int pyi = 0; pyi < 2; pyi++) {
            int py = py2 + 4 * pyi;
#pragma unroll
            for (int c2 = 0; c2 < 2; c2++) {
                int cc = 2 * ccs + c2;
                ull acc = 0ull;
                const float* cpp = rp + cc * A_CHF + 2 * px + 2;
#pragma unroll
                for (int di = 0; di < 5; di++) {
                    const float* rr = cpp + (2 * py + di) * 40;
                    FMA2(acc, mp[pyi][di][0], *(const ull*)(rr));
                    FMA2(acc, mp[pyi][di][1], *(const ull*)(rr + 2));
                    FMA2(acc, mp[pyi][di][2], *(const ull*)(rr + 4));
                }
                float a0, a1;
                unpack2(acc, a0, a1);
                ob[((size_t)(8 * i + cc) << 12) + ((h0 + py) << 6)] = a0 + a1;
            }
        }
    }
}

// ============================================================================
extern "C" void kernel_launch(void* const* d_in, const int* in_sizes, int n_in,
                              void* d_out, int out_size) {
    const float* x       = (const float*)d_in[0];
    const float* w_comp  = (const float*)d_in[1];
    const float* b_comp  = (const float*)d_in[2];
    const float* w_enc   = (const float*)d_in[3];
    const float* b_enc   = (const float*)d_in[4];
    const float* power_p = (const float*)d_in[5];
    float* out = (float*)d_out;

    cudaFuncSetAttribute(compress_kernel, cudaFuncAttributeMaxDynamicSharedMemorySize,
                         C_SMEMF * 4);
    cudaFuncSetAttribute(encoder_kernel, cudaFuncAttributeMaxDynamicSharedMemorySize,
                         E_SMEMF * 4);
    cudaFuncSetAttribute(aggregate_kernel, cudaFuncAttributeMaxDynamicSharedMemorySize,
                         A_SMEMF * 4);

    prep_kernel<<<96, 256>>>(w_comp, b_comp, w_enc, b_enc, power_p);
    compress_kernel<<<512, 256, C_SMEMF * 4>>>(x);
    encoder_kernel<<<512, 128, E_SMEMF * 4>>>();
    aggregate_kernel<<<256, 256, A_SMEMF * 4>>>(x, out);
}

// round 11
// speedup vs baseline: 2.2529x; 1.1411x over previous
#include <cuda_runtime.h>
#include <cuda_bf16.h>
#include <cstdint>

typedef unsigned long long ull;

// Problem: x (8,256,128,128) f32 -> out (8,256,64,64) f32
// CARAFE downsample, decomposed:
//   compress: cx[b,h,w,cc] (bf16, px-major) = x * w_comp + b_comp   (tf32 mma GEMM)
//   encoder:  logit = 3x3-s2 conv(cx) * exp(p)                      (tf32 mma, bf16 operands<<16)
//   softmax -> masks; aggregate: 25-tap s2 gather of x              (f32x2, LDS.128 scheme)

// ---------------- compress geometry (M=256: 2 rows/block) ----------------
#define C_XP    264
#define C_XSF   8448                 // 32*264
#define C_WBP   36
#define C_WBSF  2304                 // 64*36
#define C_SMEMF (4*C_XSF + 4*C_WBSF + 64)
// ---------------- encoder geometry (bf16 staging) ----------------
#define E_CXP   72                   // halves per px-slot (pitch, mult of 8)
#define E_SLOTS 297                  // 9 rows * 33 cols
#define E_CXH   (E_SLOTS * E_CXP)    // 21384 halves
#define E_WEP   584                  // halves per n-row
#define E_WEH   (32 * E_WEP)         // 18688 halves
#define E_SMEMB (E_CXH*2 + E_WEH*2 + 128)
// ---------------- aggregate geometry ----------------
#define A_CHF   760                  // 19 rows * 40 floats
#define A_STGF  6080                 // 8 channels per stage
#define A_NCHUNK 1520
#define A_SMEMF (4 * A_STGF)

// ---- persistent device scratch ----
__device__ float g_wb[64 * 256];              // tf32-rounded w_comp [cc][c]
__device__ __nv_bfloat16 g_web[32 * 576];     // bf16 w_enc*expP, [n][tap*64+cc]
__device__ float g_bk[32];
__device__ float g_bc[64];
__device__ float g_mask[8 * 25 * 4096];
__device__ __nv_bfloat16 g_cx[8 * 128 * 128 * 64];   // compressed feats, px-major

__device__ __forceinline__ ull pack2(float a, float b) {
    ull r; asm("mov.b64 %0, {%1, %2};" : "=l"(r) : "f"(a), "f"(b)); return r;
}
__device__ __forceinline__ void unpack2(ull v, float& a, float& b) {
    asm("mov.b64 {%0, %1}, %2;" : "=f"(a), "=f"(b) : "l"(v));
}
#define FMA2(d, a, b) asm("fma.rn.f32x2 %0, %1, %2, %0;" : "+l"(d) : "l"(a), "l"(b))

__device__ __forceinline__ uint32_t f2tf(float f) {
    uint32_t r; asm("cvt.rna.tf32.f32 %0, %1;" : "=r"(r) : "f"(f)); return r;
}
__device__ __forceinline__ void mma_tf32(float* d, const uint32_t* a, uint32_t b0, uint32_t b1) {
    asm volatile("mma.sync.aligned.m16n8k8.row.col.f32.tf32.tf32.f32 "
                 "{%0,%1,%2,%3}, {%4,%5,%6,%7}, {%8,%9}, {%0,%1,%2,%3};"
                 : "+f"(d[0]), "+f"(d[1]), "+f"(d[2]), "+f"(d[3])
                 : "r"(a[0]), "r"(a[1]), "r"(a[2]), "r"(a[3]), "r"(b0), "r"(b1));
}

__device__ __forceinline__ uint32_t smem_u32(const void* p) {
    return (uint32_t)__cvta_generic_to_shared(p);
}
__device__ __forceinline__ void cpa16(uint32_t dst, const void* src) {
    asm volatile("cp.async.ca.shared.global [%0], [%1], 16;" :: "r"(dst), "l"(src));
}
#define CP_COMMIT() asm volatile("cp.async.commit_group;")
template<int N> __device__ __forceinline__ void cp_wait() {
    asm volatile("cp.async.wait_group %0;" :: "n"(N));
}

// ============================================================================
// Kernel 1: prep. 96 blocks x 256 threads.
// ============================================================================
__global__ void prep_kernel(const float* __restrict__ w_comp, const float* __restrict__ b_comp,
                            const float* __restrict__ w_enc, const float* __restrict__ b_enc,
                            const float* __restrict__ power_p) {
    int bid = blockIdx.x, t = threadIdx.x;
    float expP = __expf(power_p[0]);
    if (bid < 64) {
        g_wb[bid * 256 + t] = __uint_as_float(f2tf(w_comp[bid * 256 + t]));
    } else {
        int n = bid - 64;
        for (int i = t; i < 576; i += 256) {
            float v = 0.f;
            if (n < 25) {
                int cc = i & 63, tap = i >> 6;
                v = w_enc[((n * 64 + cc) * 9) + tap] * expP;
            }
            g_web[n * 576 + i] = __float2bfloat16(v);
        }
        if (n == 0 && t < 32) g_bk[t] = (t < 25) ? b_enc[t] * expP : 0.f;
        if (n == 1 && t < 64) g_bc[t] = b_comp[t];
    }
}

// ============================================================================
// Kernel 2: compress GEMM. 512 blocks (2 rows each), 256 threads.
// M=256, N=64, K=256; tf32 m16n8k8; epilogue: bf16 tile in smem -> coalesced STG.
// ============================================================================
__global__ __launch_bounds__(256) void compress_kernel(const float* __restrict__ x) {
    extern __shared__ __align__(16) float SM[];
    int bid = blockIdx.x;
    int b = bid >> 6, h2 = bid & 63;
    int tid = threadIdx.x;
    int wid = tid >> 5, lane = tid & 31;
    int g = lane >> 2, tig = lane & 3;

    float* XS  = SM;
    float* WBS = SM + 4 * C_XSF;
    float* BC  = SM + 4 * C_XSF + 4 * C_WBSF;

    if (tid < 64) BC[tid] = g_bc[tid];

    uint32_t xsa = smem_u32(XS), wba = smem_u32(WBS);
    const float* xb = x + ((size_t)b * 256) * 16384 + h2 * 256;

    auto fill = [&](int s, int kc) {
        const float* xc = xb + (size_t)(kc * 32) * 16384;
        uint32_t xd = xsa + (uint32_t)s * (C_XSF * 4);
#pragma unroll
        for (int j = 0; j < 8; j++) {
            int idx = tid + j * 256;
            int c = idx >> 6, q = idx & 63;
            cpa16(xd + (uint32_t)(c * C_XP + 4 * q) * 4, xc + (size_t)c * 16384 + 4 * q);
        }
        uint32_t wd = wba + (uint32_t)s * (C_WBSF * 4);
#pragma unroll
        for (int j = 0; j < 2; j++) {
            int idx = tid + j * 256;
            int cc = idx >> 3, q = idx & 7;
            cpa16(wd + (uint32_t)(cc * C_WBP + 4 * q) * 4, g_wb + cc * 256 + kc * 32 + 4 * q);
        }
    };

    float d[2][8][4];
#pragma unroll
    for (int mt = 0; mt < 2; mt++)
#pragma unroll
        for (int nt = 0; nt < 8; nt++)
#pragma unroll
            for (int j = 0; j < 4; j++) d[mt][nt][j] = 0.f;

    fill(0, 0); CP_COMMIT();
    fill(1, 1); CP_COMMIT();
#pragma unroll 1
    for (int i = 0; i < 8; i++) {
        if (i + 2 < 8) fill((i + 2) & 3, i + 2);
        CP_COMMIT();
        cp_wait<2>();
        __syncthreads();

        const float* xs = XS + (i & 3) * C_XSF;
        const uint32_t* wbs = (const uint32_t*)(WBS + (i & 3) * C_WBSF);
#pragma unroll
        for (int k8 = 0; k8 < 4; k8++) {
            int cb = k8 * 8;
            uint32_t a[2][4];
#pragma unroll
            for (int mt = 0; mt < 2; mt++) {
                int pxl = 32 * wid + 16 * mt + g;
                a[mt][0] = f2tf(xs[(cb + tig) * C_XP + pxl]);
                a[mt][1] = f2tf(xs[(cb + tig) * C_XP + pxl + 8]);
                a[mt][2] = f2tf(xs[(cb + tig + 4) * C_XP + pxl]);
                a[mt][3] = f2tf(xs[(cb + tig + 4) * C_XP + pxl + 8]);
            }
#pragma unroll
            for (int nt = 0; nt < 8; nt++) {
                uint32_t b0 = wbs[(8 * nt + g) * C_WBP + cb + tig];
                uint32_t b1 = wbs[(8 * nt + g) * C_WBP + cb + tig + 4];
                mma_tf32(d[0][nt], a[0], b0, b1);
                mma_tf32(d[1][nt], a[1], b0, b1);
            }
        }
    }

    // epilogue: bf16 tile in smem, then coalesced 16B-per-lane store
    __syncthreads();
    uint32_t* CXT32 = (uint32_t*)SM;     // 256 px x 32 u32 (bf16 pairs)
#pragma unroll
    for (int mt = 0; mt < 2; mt++) {
#pragma unroll
        for (int nt = 0; nt < 8; nt++) {
            int pxl = 32 * wid + 16 * mt + g;
            int cc = 8 * nt + 2 * tig;
            float bc0 = BC[cc], bc1 = BC[cc + 1];
            __nv_bfloat162 p0 = __floats2bfloat162_rn(d[mt][nt][0] + bc0, d[mt][nt][1] + bc1);
            __nv_bfloat162 p1 = __floats2bfloat162_rn(d[mt][nt][2] + bc0, d[mt][nt][3] + bc1);
            CXT32[pxl * 32 + (cc >> 1)]       = *(uint32_t*)&p0;
            CXT32[(pxl + 8) * 32 + (cc >> 1)] = *(uint32_t*)&p1;
        }
    }
    __syncthreads();
    const uint4* srcq = (const uint4*)SM;
    uint4* dstq = (uint4*)(g_cx + (size_t)bid * 16384);
#pragma unroll
    for (int j = 0; j < 8; j++)
        dstq[tid + j * 256] = srcq[tid + j * 256];
}

// ============================================================================
// Kernel 3: encoder GEMM + softmax -> g_mask. 512 blocks (16w x 4h out tiles),
// 128 threads. M=64 px, N=32, K=576. bf16 staging, tf32 mma via <<16.
// ============================================================================
__global__ __launch_bounds__(128) void encoder_kernel() {
    extern __shared__ __align__(16) char SMC[];
    unsigned short* CXS = (unsigned short*)SMC;
    unsigned short* WES = (unsigned short*)(SMC + E_CXH * 2);
    float* BKS = (float*)(SMC + E_CXH * 2 + E_WEH * 2);

    int bid = blockIdx.x;
    int b = bid >> 6, t = bid & 63;
    int w0 = (t & 3) * 16;
    int h0 = (t >> 2) * 4;
    int tid = threadIdx.x;
    int wid = tid >> 5, lane = tid & 31;
    int g = lane >> 2, tig = lane & 3;

    // zero cx staging (borders stay zero)
    uint32_t* cz = (uint32_t*)CXS;
    for (int i = tid; i < E_CXH / 2; i += 128) cz[i] = 0u;
    if (tid < 32) BKS[tid] = g_bk[tid];
    __syncthreads();

    uint32_t cxa = smem_u32(CXS), wea = smem_u32(WES);
    // weights: 32 n-rows x 72 chunks of 8 halves
#pragma unroll 4
    for (int j = 0; j < 18; j++) {
        int idx = tid + j * 128;
        int n = idx / 72, q = idx - n * 72;
        cpa16(wea + (uint32_t)(n * E_WEP + 8 * q) * 2, g_web + n * 576 + 8 * q);
    }
    // cx patch: 297 slots x 8 chunks = 2376 chunks
#pragma unroll 4
    for (int j = 0; j < 19; j++) {
        int idx = tid + j * 128;
        if (idx < 2376) {
            int slot = idx >> 3, q = idx & 7;
            int r = slot / 33, pi = slot - r * 33;
            int hr = 2 * h0 - 1 + r;
            int wc = 2 * w0 - 1 + pi;
            if (hr >= 0 && hr < 128 && wc >= 0 && wc < 128)
                cpa16(cxa + (uint32_t)(slot * E_CXP + 8 * q) * 2,
                      g_cx + ((size_t)(b * 128 + hr) * 128 + wc) * 64 + 8 * q);
        }
    }
    CP_COMMIT();
    cp_wait<0>();
    __syncthreads();

    float d[4][4];
#pragma unroll
    for (int nt = 0; nt < 4; nt++)
#pragma unroll
        for (int j = 0; j < 4; j++) d[nt][j] = 0.f;

#pragma unroll 1
    for (int tap = 0; tap < 9; tap++) {
        int dy = tap / 3, dx = tap % 3;
        const unsigned short* baseL = CXS + ((2 * wid + dy) * 33 + (2 * g + dx)) * E_CXP;
        const unsigned short* baseH = baseL + 16 * E_CXP;
#pragma unroll
        for (int kc = 0; kc < 8; kc++) {
            int cb = kc * 8;
            uint32_t a[4];
            a[0] = ((uint32_t)baseL[cb + tig]) << 16;
            a[1] = ((uint32_t)baseH[cb + tig]) << 16;
            a[2] = ((uint32_t)baseL[cb + tig + 4]) << 16;
            a[3] = ((uint32_t)baseH[cb + tig + 4]) << 16;
            int ko = tap * 64 + cb + tig;
#pragma unroll
            for (int nt = 0; nt < 4; nt++) {
                uint32_t b0 = ((uint32_t)WES[(8 * nt + g) * E_WEP + ko]) << 16;
                uint32_t b1 = ((uint32_t)WES[(8 * nt + g) * E_WEP + ko + 4]) << 16;
                mma_tf32(d[nt], a, b0, b1);
            }
        }
    }

    int hh = h0 + wid;
#pragma unroll
    for (int half = 0; half < 2; half++) {
        int ww = w0 + g + 8 * half;
        float lg[8];
#pragma unroll
        for (int nt = 0; nt < 4; nt++) {
#pragma unroll
            for (int j = 0; j < 2; j++) {
                int n = 8 * nt + 2 * tig + j;
                float v = d[nt][2 * half + j];
                lg[nt * 2 + j] = (n < 25) ? (v + BKS[n]) : -1e30f;
            }
        }
        float mx = lg[0];
#pragma unroll
        for (int j = 1; j < 8; j++) mx = fmaxf(mx, lg[j]);
        mx = fmaxf(mx, __shfl_xor_sync(0xffffffffu, mx, 1));
        mx = fmaxf(mx, __shfl_xor_sync(0xffffffffu, mx, 2));
        float sum = 0.f;
#pragma unroll
        for (int j = 0; j < 8; j++) { lg[j] = __expf(lg[j] - mx); sum += lg[j]; }
        sum += __shfl_xor_sync(0xffffffffu, sum, 1);
        sum += __shfl_xor_sync(0xffffffffu, sum, 2);
        float inv = 1.f / sum;
#pragma unroll
        for (int nt = 0; nt < 4; nt++) {
#pragma unroll
            for (int j = 0; j < 2; j++) {
                int n = 8 * nt + 2 * tig + j;
                if (n < 25)
                    g_mask[((b * 25 + n) << 12) + (hh << 6) + ww] = lg[nt * 2 + j] * inv;
            }
        }
    }
}

// ============================================================================
// Kernel 4: 25-tap s2 gather. 256 blocks (16w x 8h tiles), 256 threads.
// lane = pxp(8) x ccs(4), warp = py(8). Thread: px pair via LDS.128 scheme.
// 8 ch/stage, 32 iters, 4-stage cp.async, one barrier/iter.
// ============================================================================
__global__ __launch_bounds__(256) void aggregate_kernel(const float* __restrict__ x,
                                                        float* __restrict__ out) {
    extern __shared__ __align__(16) float AS[];
    int bid = blockIdx.x;
    int b = bid >> 5;
    int t = bid & 31;
    int w0 = (t & 3) * 16;
    int h0 = (t >> 2) * 8;
    int tid = threadIdx.x;
    int pxp = tid & 7;
    int ccs = (tid >> 3) & 3;
    int py  = tid >> 5;
    int h = h0 + py;
    int wbase = w0 + 2 * pxp;

    for (int i = tid; i < A_SMEMF; i += 256) AS[i] = 0.f;

    uint32_t asa = smem_u32(AS);
    const float* xb = x + (size_t)b * 256 * 16384;

    // masks for px pair (wbase, wbase+1), packed spatial tap-pairs
    ull mp[2][5][3];
#pragma unroll
    for (int e = 0; e < 2; e++) {
        int w = wbase + e;
        float m[25];
#pragma unroll
        for (int k = 0; k < 25; k++)
            m[k] = g_mask[((b * 25 + k) << 12) + (h << 6) + w];
#pragma unroll
        for (int di = 0; di < 5; di++) {
            mp[e][di][0] = pack2(m[5 * di],     m[5 * di + 1]);
            mp[e][di][1] = pack2(m[5 * di + 2], m[5 * di + 3]);
            mp[e][di][2] = pack2(m[5 * di + 4], 0.f);
        }
    }

    auto fill = [&](int s, int ci) {      // ci: channel group of 8
        const float* xc = xb + (size_t)(8 * ci) * 16384;
        uint32_t base = asa + (uint32_t)s * (A_STGF * 4);
#pragma unroll
        for (int j = 0; j < 6; j++) {
            int idx = tid + j * 256;
            if (idx < A_NCHUNK) {
                int ch = idx / 190; int rem = idx - ch * 190;
                int r = rem / 10;   int q = rem - r * 10;
                int row = 2 * h0 - 2 + r;
                int col = 2 * w0 - 4 + 4 * q;
                if (row >= 0 && row < 128 && col >= 0 && col <= 124)
                    cpa16(base + (uint32_t)(ch * A_CHF + r * 40 + 4 * q) * 4,
                          xc + (size_t)ch * 16384 + (row << 7) + col);
            }
        }
    };

    float* ob = out + (((size_t)b * 256) << 12) + (h << 6) + wbase;
    __syncthreads();
    fill(0, 0); CP_COMMIT();
    fill(1, 1); CP_COMMIT();

#pragma unroll 1
    for (int i = 0; i < 32; i++) {
        if (i + 2 < 32) fill((i + 2) & 3, i + 2);
        CP_COMMIT();
        cp_wait<2>();
        __syncthreads();

        const float* rp = AS + (i & 3) * A_STGF;
#pragma unroll
        for (int sub = 0; sub < 2; sub++) {
            int ch = ccs + 4 * sub;
            const float* cpp = rp + ch * A_CHF + 4 * pxp;
            ull accA = 0ull, accB = 0ull;
#pragma unroll
            for (int di = 0; di < 5; di++) {
                const float* rr = cpp + (2 * py + di) * 40;
                ulonglong2 q0 = *(const ulonglong2*)(rr);       // f0..f3
                ulonglong2 q1 = *(const ulonglong2*)(rr + 4);   // f4..f7
                ull d2 = *(const ull*)(rr + 8);                 // f8,f9
                FMA2(accA, mp[0][di][0], q0.y);
                FMA2(accA, mp[0][di][1], q1.x);
                FMA2(accA, mp[0][di][2], q1.y);
                FMA2(accB, mp[1][di][0], q1.x);
                FMA2(accB, mp[1][di][1], q1.y);
                FMA2(accB, mp[1][di][2], d2);
            }
            float a0, a1, b0, b1;
            unpack2(accA, a0, a1);
            unpack2(accB, b0, b1);
            *(float2*)(ob + ((size_t)(8 * i + ch) << 12)) = make_float2(a0 + a1, b0 + b1);
        }
    }
}

// ============================================================================
extern "C" void kernel_launch(void* const* d_in, const int* in_sizes, int n_in,
                              void* d_out, int out_size) {
    const float* x       = (const float*)d_in[0];
    const float* w_comp  = (const float*)d_in[1];
    const float* b_comp  = (const float*)d_in[2];
    const float* w_enc   = (const float*)d_in[3];
    const float* b_enc   = (const float*)d_in[4];
    const float* power_p = (const float*)d_in[5];
    float* out = (float*)d_out;

    cudaFuncSetAttribute(compress_kernel, cudaFuncAttributeMaxDynamicSharedMemorySize,
                         C_SMEMF * 4);
    cudaFuncSetAttribute(encoder_kernel, cudaFuncAttributeMaxDynamicSharedMemorySize,
                         E_SMEMB);
    cudaFuncSetAttribute(aggregate_kernel, cudaFuncAttributeMaxDynamicSharedMemorySize,
                         A_SMEMF * 4);

    prep_kernel<<<96, 256>>>(w_comp, b_comp, w_enc, b_enc, power_p);
    compress_kernel<<<512, 256, C_SMEMF * 4>>>(x);
    encoder_kernel<<<512, 128, E_SMEMB>>>();
    aggregate_kernel<<<256, 256, A_SMEMF * 4>>>(x, out);
}